// round 15
// baseline (speedup 1.0000x reference)
#include <cuda_runtime.h>
#include <cuda_bf16.h>
#include <cuda_fp16.h>
#include <cstdint>

// AFM layer via mma.sync (sm_80-class HMMA on sm_100 target). 2 CTAs/SM.
// B=1024, N=64 fields, E=64, A=32, P=2016 pairs.
//   Phase 1: logits = relu(inner@W1 + b1)@W2 + b2, fp16 mma 2-term split.
//            SPLIT ACCUMULATORS: hi-term -> c[], lo-term -> cl[] (8 indep
//            4-long HMMA chains per warp instead of 4x8). bh hoisted in regs,
//            bl read from conflict-free stride-40 smem.
//            XSTR=80: conflict-free LDS.128 xj loads.
//   Phase 2: softmax (__expf) + scatter symmetric attn matrix.
//   Phase 3: out = 0.5 * colsum( x .* (W@x) ), bf16 3-term mma.

#define NF 64
#define EDIM 64
#define ADIM 32
#define NPAIR 2016
#define XSTR 80        // 16B-chunk stride 4 mod 8 -> LDS.128 conflict-free
#define XPS 72
#define WPS 44
#define W1LS 40        // W1l row stride (words): bank 8(tg+nb)+gr distinct
#define NTHREADS 256
#define NSEGT 160

// dynamic smem layout (bytes)
#define OFF_XS   0          // float[64*80]  = 20480 (PERMUTED cols)
#define OFF_W1H  20480      // u32[32*33]    = 4224  (fp16x2 hi; hoist-only)
#define OFF_W1L  24704      // u32[32*40]    = 5120  (fp16x2 lo; loop-read)
#define OFF_LG   29824      // float[2048]   = 8192
#define OFF_IJP  38016      // u16[2048]     = 4096
#define OFF_XPH  42112      // u32[32*72]    = 9216
#define OFF_XPL  51328      // u32[32*72]    = 9216
#define OFF_WPH  60544      // u32[64*44]    = 11264
#define OFF_WPL  71808      // u32[64*44]    = 11264
#define OFF_SEG  83072      // u32[160]      = 640
#define OFF_MISC 83712      // bwq float4[16] (256) + red[8] (32) + b2 (4)
#define SMEM_DYN 84032

typedef unsigned long long ull;

__device__ __forceinline__ void up2(ull v, float& lo, float& hi) {
    asm("mov.b64 {%0, %1}, %2;" : "=f"(lo), "=f"(hi) : "l"(v));
}
__device__ __forceinline__ ull fma2(ull a, ull b, ull c) {
    ull d; asm("fma.rn.f32x2 %0, %1, %2, %3;" : "=l"(d) : "l"(a), "l"(b), "l"(c)); return d;
}
__device__ __forceinline__ uint32_t bf2(float vhi, float vlo) {
    uint32_t r; asm("cvt.rn.bf16x2.f32 %0, %1, %2;" : "=r"(r) : "f"(vhi), "f"(vlo)); return r;
}
__device__ __forceinline__ uint32_t hf2(float vhi, float vlo) {
    uint32_t r; asm("cvt.rn.f16x2.f32 %0, %1, %2;" : "=r"(r) : "f"(vhi), "f"(vlo)); return r;
}
__device__ __forceinline__ void mma_h(float* c, uint32_t a0, uint32_t a1,
                                      uint32_t a2, uint32_t a3,
                                      uint32_t b0, uint32_t b1) {
    asm volatile(
        "mma.sync.aligned.m16n8k16.row.col.f32.f16.f16.f32 "
        "{%0,%1,%2,%3}, {%4,%5,%6,%7}, {%8,%9}, {%0,%1,%2,%3};"
        : "+f"(c[0]), "+f"(c[1]), "+f"(c[2]), "+f"(c[3])
        : "r"(a0), "r"(a1), "r"(a2), "r"(a3), "r"(b0), "r"(b1));
}
__device__ __forceinline__ void mma_b(float* c, uint32_t a0, uint32_t a1,
                                      uint32_t a2, uint32_t a3,
                                      uint32_t b0, uint32_t b1) {
    asm volatile(
        "mma.sync.aligned.m16n8k16.row.col.f32.bf16.bf16.f32 "
        "{%0,%1,%2,%3}, {%4,%5,%6,%7}, {%8,%9}, {%0,%1,%2,%3};"
        : "+f"(c[0]), "+f"(c[1]), "+f"(c[2]), "+f"(c[3])
        : "r"(a0), "r"(a1), "r"(a2), "r"(a3), "r"(b0), "r"(b1));
}
// column permutation within a 16-block: [0,1,8,9, 2,3,10,11, 4,5,12,13, 6,7,14,15]
__device__ __forceinline__ int pcol(int e) {
    int w = e & 15;
    return (e & 48) + ((w >> 1) & 3) * 4 + (w & 1) + ((w >> 3) << 1);
}

__global__ __launch_bounds__(NTHREADS, 2)
void afm_kernel(const float* __restrict__ x,    // (B, 64, 64)
                const float* __restrict__ W1,   // (64, 32)
                const float* __restrict__ b1,   // (32)
                const float* __restrict__ W2,   // (32, 1)
                const float* __restrict__ b2,   // (1)
                float* __restrict__ outP,       // (B, 64) or null
                float* __restrict__ attnP)      // (B, 2016) or null
{
    extern __shared__ char smx[];
    float*          xs   = (float*)(smx + OFF_XS);      // permuted
    uint32_t*       W1h  = (uint32_t*)(smx + OFF_W1H);
    uint32_t*       W1l  = (uint32_t*)(smx + OFF_W1L);
    float*          lg   = (float*)(smx + OFF_LG);
    unsigned short* ijp  = (unsigned short*)(smx + OFF_IJP);
    uint32_t*       Xph  = (uint32_t*)(smx + OFF_XPH);
    uint32_t*       Xpl  = (uint32_t*)(smx + OFF_XPL);
    uint32_t*       Wph  = (uint32_t*)(smx + OFF_WPH);
    uint32_t*       Wpl  = (uint32_t*)(smx + OFF_WPL);
    uint32_t*       segt = (uint32_t*)(smx + OFF_SEG);
    uint16_t*       Wph16 = (uint16_t*)Wph;
    uint16_t*       Wpl16 = (uint16_t*)Wpl;
    float4*         bwq  = (float4*)(smx + OFF_MISC);   // {b1[2k],w2[2k],b1[2k+1],w2[2k+1]}
    float*          red  = (float*)(smx + OFF_MISC + 256);
    float*          b2sp = red + 8;

    const int t    = threadIdx.x;
    const int lane = t & 31;
    const int warp = t >> 5;
    const int b    = blockIdx.x;

    // ======================= prologue ======================================
    const float* xb = x + (size_t)b * (NF * EDIM);
    for (int idx = t; idx < NF * EDIM; idx += NTHREADS) {
        int f = idx >> 6, e = idx & 63;
        xs[f * XSTR + pcol(e)] = xb[idx];
    }
    // Xp: packed bf16x2 over field pairs (phase 3 operand)
    for (int idx = t; idx < 32 * 64; idx += NTHREADS) {
        int j2 = idx >> 6, e = idx & 63;
        float v0 = xb[(2 * j2) * EDIM + e];
        float v1 = xb[(2 * j2 + 1) * EDIM + e];
        uint32_t hi = bf2(v1, v0);
        float h0 = __uint_as_float(hi << 16);
        float h1 = __uint_as_float(hi & 0xFFFF0000u);
        Xph[j2 * XPS + e] = hi;
        Xpl[j2 * XPS + e] = bf2(v1 - h1, v0 - h0);
    }
    // W1 fp16 hi/lo: word[e2][a] = {W1[2e2+1][a] hi-half, W1[2e2][a] lo-half}
    for (int idx = t; idx < 32 * 32; idx += NTHREADS) {
        int e2 = idx >> 5, a = idx & 31;
        float v0 = W1[(2 * e2) * ADIM + a];
        float v1 = W1[(2 * e2 + 1) * ADIM + a];
        uint32_t hi = hf2(v1, v0);
        __half2 h2 = *(__half2*)&hi;
        float2 back = __half22float2(h2);
        W1h[e2 * 33 + a] = hi;
        W1l[e2 * W1LS + a] = hf2(v1 - back.y, v0 - back.x);
    }
    // zero attn matrices
    for (int idx = t; idx < 64 * WPS; idx += NTHREADS) {
        Wph[idx] = 0u;
        Wpl[idx] = 0u;
    }
    if (t < 16) bwq[t] = make_float4(b1[2 * t], W2[2 * t], b1[2 * t + 1], W2[2 * t + 1]);
    if (t == 0) b2sp[0] = b2[0];
    // pair table + segment table
    if (t < NF - 1) {
        int i = t;
        int offi = i * 63 - (i * (i - 1)) / 2;
        for (int k = 0; k < NF - 1 - i; k++)
            ijp[offi + k] = (unsigned short)((i << 8) | (i + 1 + k));
        int q = i >> 4, r = i & 15;
        int S = 16 * (q * (q - 1) / 2) + q * (r + 1);
        int segbase = 4 * i - S;
        int first = (i + 1) >> 4;
        for (int s = first; s < 4; s++)
            segt[segbase + (s - first)] =
                (uint32_t)i | ((uint32_t)s << 6) | ((uint32_t)offi << 8);
    }
    if (t == 63) {
        for (int s = 0; s < 4; s++) segt[156 + s] = 63u | (3u << 6);
    }
    if (t >= 224) ijp[NPAIR + (t - 224)] = 0;
    __syncthreads();

    const float b2v = b2sp[0];
    const int tg = lane & 3;
    const int gr = lane >> 2;

    // hoist ONLY bh fragments (32 regs); bl from smem per tile
    uint32_t bh0[4][4], bh1[4][4];
    #pragma unroll
    for (int kb = 0; kb < 4; kb++) {
        #pragma unroll
        for (int nb = 0; nb < 4; nb++) {
            int e2 = kb * 8 + tg;
            int a  = nb * 8 + gr;
            bh0[kb][nb] = W1h[e2 * 33 + a];
            bh1[kb][nb] = W1h[(e2 + 4) * 33 + a];
        }
    }

    // ================= Phase 1: logits via fp16 mma (segments) =============
    for (int tt = 0; tt < NSEGT / 8; tt++) {
        const uint32_t sv = segt[tt * 8 + warp];
        const int i    = sv & 63;
        const int jb   = ((sv >> 6) & 3) << 4;
        const int offi = sv >> 8;

        const ulonglong2* xiP  = (const ulonglong2*)(xs + i * XSTR) + tg;
        const ulonglong2* xj0P = (const ulonglong2*)(xs + (jb + gr) * XSTR) + tg;
        const ulonglong2* xj1P = (const ulonglong2*)(xs + (jb + gr + 8) * XSTR) + tg;

        float c[4][4], cl[4][4];
        #pragma unroll
        for (int nb = 0; nb < 4; nb++) {
            c[nb][0] = c[nb][1] = c[nb][2] = c[nb][3] = 0.f;
            cl[nb][0] = cl[nb][1] = cl[nb][2] = cl[nb][3] = 0.f;
        }

        #pragma unroll
        for (int kb = 0; kb < 4; kb++) {
            const ulonglong2 xiv = xiP[kb * 4];
            const ulonglong2 xj0 = xj0P[kb * 4];
            const ulonglong2 xj1 = xj1P[kb * 4];
            ull prA = fma2(xj0.x, xiv.x, 0ull);
            ull prB = fma2(xj0.y, xiv.y, 0ull);
            ull prC = fma2(xj1.x, xiv.x, 0ull);
            ull prD = fma2(xj1.y, xiv.y, 0ull);
            float v0, v1;
            up2(prA, v0, v1); const uint32_t a0 = hf2(v1, v0);
            up2(prC, v0, v1); const uint32_t a1 = hf2(v1, v0);
            up2(prB, v0, v1); const uint32_t a2 = hf2(v1, v0);
            up2(prD, v0, v1); const uint32_t a3 = hf2(v1, v0);
            const uint32_t* wlA = W1l + (kb * 8 + tg) * W1LS;
            const uint32_t* wlB = wlA + 4 * W1LS;
            #pragma unroll
            for (int nb = 0; nb < 4; nb++) {
                const int a = nb * 8 + gr;
                mma_h(c[nb],  a0, a1, a2, a3, bh0[kb][nb], bh1[kb][nb]);  // hi chain
                mma_h(cl[nb], a0, a1, a2, a3, wlA[a], wlB[a]);            // lo chain
            }
        }

        float s_lo = 0.f, s_hi = 0.f;
        #pragma unroll
        for (int nb = 0; nb < 4; nb++) {
            const float4 q = bwq[nb * 4 + tg];   // {b1[a],w2[a],b1[a+1],w2[a+1]}, a=nb*8+tg*2
            s_lo = fmaf(fmaxf(c[nb][0] + cl[nb][0] + q.x, 0.f), q.y, s_lo);
            s_lo = fmaf(fmaxf(c[nb][1] + cl[nb][1] + q.z, 0.f), q.w, s_lo);
            s_hi = fmaf(fmaxf(c[nb][2] + cl[nb][2] + q.x, 0.f), q.y, s_hi);
            s_hi = fmaf(fmaxf(c[nb][3] + cl[nb][3] + q.z, 0.f), q.w, s_hi);
        }
        s_lo += __shfl_xor_sync(0xFFFFFFFFu, s_lo, 1);
        s_lo += __shfl_xor_sync(0xFFFFFFFFu, s_lo, 2);
        s_hi += __shfl_xor_sync(0xFFFFFFFFu, s_hi, 1);
        s_hi += __shfl_xor_sync(0xFFFFFFFFu, s_hi, 2);
        if (tg == 0) {
            const int j0 = jb + gr;
            const int j1 = jb + gr + 8;
            if (j0 > i) lg[offi + j0 - i - 1] = s_lo + b2v;
            if (j1 > i) lg[offi + j1 - i - 1] = s_hi + b2v;
        }
    }
    __syncthreads();

    // ================= Phase 2: softmax ====================================
    float lmax = -3.402823466e+38f;
    for (int p = t; p < NPAIR; p += NTHREADS) lmax = fmaxf(lmax, lg[p]);
    #pragma unroll
    for (int o = 16; o > 0; o >>= 1) lmax = fmaxf(lmax, __shfl_xor_sync(0xFFFFFFFFu, lmax, o));
    if (lane == 0) red[warp] = lmax;
    __syncthreads();
    if (t == 0) {
        float m = red[0];
        #pragma unroll
        for (int w = 1; w < 8; w++) m = fmaxf(m, red[w]);
        red[0] = m;
    }
    __syncthreads();
    const float gmax = red[0];
    __syncthreads();

    float lsum = 0.f;
    for (int p = t; p < NPAIR; p += NTHREADS) {
        float ev = __expf(lg[p] - gmax);
        lg[p] = ev;
        lsum += ev;
    }
    #pragma unroll
    for (int o = 16; o > 0; o >>= 1) lsum += __shfl_xor_sync(0xFFFFFFFFu, lsum, o);
    if (lane == 0) red[warp] = lsum;
    __syncthreads();
    if (t == 0) {
        float s = 0.f;
        #pragma unroll
        for (int w = 0; w < 8; w++) s += red[w];
        red[0] = 1.0f / s;
    }
    __syncthreads();
    const float inv = red[0];

    // normalize + emit attn + scatter symmetric W (bf16 hi/lo)
    for (int p = t; p < NPAIR; p += NTHREADS) {
        float av = lg[p] * inv;
        if (attnP) attnP[(size_t)b * NPAIR + p] = av;
        const unsigned short ij = ijp[p];
        const int i = ij >> 8, j = ij & 255;
        uint32_t hpair = bf2(0.f, av);
        uint16_t hb = (uint16_t)(hpair & 0xFFFFu);
        float hv = __uint_as_float((uint32_t)hb << 16);
        uint32_t lpair = bf2(0.f, av - hv);
        uint16_t lb = (uint16_t)(lpair & 0xFFFFu);
        Wph16[i * (2 * WPS) + j] = hb;
        Wph16[j * (2 * WPS) + i] = hb;
        Wpl16[i * (2 * WPS) + j] = lb;
        Wpl16[j * (2 * WPS) + i] = lb;
    }
    __syncthreads();

    // ================= Phase 3: out = 0.5 * colsum(x .* (W@x)) =============
    if (outP) {
        float c[4][4];
        #pragma unroll
        for (int m = 0; m < 4; m++)
            c[m][0] = c[m][1] = c[m][2] = c[m][3] = 0.f;

        const int ecol = warp * 8 + gr;
        #pragma unroll
        for (int kb = 0; kb < 4; kb++) {
            const int j2a = kb * 8 + tg;
            uint32_t xh0 = Xph[j2a * XPS + ecol];
            uint32_t xh1 = Xph[(j2a + 4) * XPS + ecol];
            uint32_t xl0 = Xpl[j2a * XPS + ecol];
            uint32_t xl1 = Xpl[(j2a + 4) * XPS + ecol];
            #pragma unroll
            for (int m = 0; m < 4; m++) {
                const int r0 = (m * 16 + gr) * WPS;
                const int r1 = (m * 16 + gr + 8) * WPS;
                uint32_t ah0 = Wph[r0 + j2a];
                uint32_t ah1 = Wph[r1 + j2a];
                uint32_t ah2 = Wph[r0 + j2a + 4];
                uint32_t ah3 = Wph[r1 + j2a + 4];
                uint32_t al0 = Wpl[r0 + j2a];
                uint32_t al1 = Wpl[r1 + j2a];
                uint32_t al2 = Wpl[r0 + j2a + 4];
                uint32_t al3 = Wpl[r1 + j2a + 4];
                mma_b(c[m], ah0, ah1, ah2, ah3, xh0, xh1);
                mma_b(c[m], ah0, ah1, ah2, ah3, xl0, xl1);
                mma_b(c[m], al0, al1, al2, al3, xh0, xh1);
            }
        }

        const int e0 = warp * 8 + tg * 2;
        const int pe = pcol(e0);
        float pe0 = 0.f, pe1 = 0.f;
        #pragma unroll
        for (int m = 0; m < 4; m++) {
            const int i0 = m * 16 + gr;
            const int i1 = i0 + 8;
            float x00, x01, x10, x11;
            up2(*(const ull*)(xs + i0 * XSTR + pe), x00, x01);
            up2(*(const ull*)(xs + i1 * XSTR + pe), x10, x11);
            pe0 = fmaf(c[m][0], x00, pe0);
            pe1 = fmaf(c[m][1], x01, pe1);
            pe0 = fmaf(c[m][2], x10, pe0);
            pe1 = fmaf(c[m][3], x11, pe1);
        }
        #pragma unroll
        for (int o = 4; o < 32; o <<= 1) {
            pe0 += __shfl_xor_sync(0xFFFFFFFFu, pe0, o);
            pe1 += __shfl_xor_sync(0xFFFFFFFFu, pe1, o);
        }
        if (gr == 0) {
            outP[(size_t)b * EDIM + e0]     = 0.5f * pe0;
            outP[(size_t)b * EDIM + e0 + 1] = 0.5f * pe1;
        }
    }
}

extern "C" void kernel_launch(void* const* d_in, const int* in_sizes, int n_in,
                              void* d_out, int out_size) {
    const float* x  = (const float*)d_in[0];
    const float* W1 = (const float*)d_in[1];
    const float* b1 = (const float*)d_in[2];
    const float* W2 = (const float*)d_in[3];
    const float* b2 = (const float*)d_in[4];

    const int B = in_sizes[0] / (NF * EDIM);

    float* outP  = (float*)d_out;
    float* attnP = (float*)d_out + (size_t)B * EDIM;
    if (out_size == B * NPAIR) {           // attn only
        attnP = (float*)d_out;
        outP  = nullptr;
    } else if (out_size == B * EDIM) {     // outputs only
        attnP = nullptr;
    }

    cudaFuncSetAttribute(afm_kernel, cudaFuncAttributeMaxDynamicSharedMemorySize, SMEM_DYN);
    afm_kernel<<<B, NTHREADS, SMEM_DYN>>>(x, W1, b1, W2, b2, outP, attnP);
}

// round 16
// speedup vs baseline: 1.1757x; 1.1757x over previous
#include <cuda_runtime.h>
#include <cuda_bf16.h>
#include <cuda_fp16.h>
#include <cstdint>

// AFM layer via mma.sync (sm_80-class HMMA on sm_100 target). 2 CTAs/SM.
// B=1024, N=64 fields, E=64, A=32, P=2016 pairs.
//   Phase 1: logits = relu(inner@W1 + b1)@W2 + b2, fp16 mma 2-term split.
//            A fragments built by mul.f16x2 on an fp16 x tile (no fp32
//            product/convert chain). W1 hi+lo hoisted in registers.
//   Phase 2: softmax (__expf) + scatter symmetric attn matrix.
//   Phase 3: out = 0.5 * colsum( x .* (W@x) ), bf16 3-term mma (fp32 xs).

#define NF 64
#define EDIM 64
#define ADIM 32
#define NPAIR 2016
#define XSTR 80        // fp32 xs: 16B-chunk stride 4 mod 8 -> LDS.128 conflict-free
#define XHB 160        // fp16 xh row stride BYTES: 8B-chunk stride 20 -> 4r+tg mod 16, conflict-free LDS.64
#define XPS 72
#define WPS 44
#define NTHREADS 256
#define NSEGT 160

// dynamic smem layout (bytes)
#define OFF_XS   0          // float[64*80]  = 20480 (PERMUTED cols)
#define OFF_W1H  20480      // u32[32*33]    = 4224  (fp16x2 hi)
#define OFF_W1L  24704      // u32[32*33]    = 4224  (fp16x2 lo)
#define OFF_LG   28928      // float[2048]   = 8192
#define OFF_IJP  37120      // u16[2048]     = 4096
#define OFF_XPH  41216      // u32[32*72]    = 9216
#define OFF_XPL  50432      // u32[32*72]    = 9216
#define OFF_WPH  59648      // u32[64*44]    = 11264
#define OFF_WPL  70912      // u32[64*44]    = 11264
#define OFF_SEG  82176      // u32[160]      = 640
#define OFF_MISC 82816      // bwq float4[16] (256) + red[8] (32) + b2 (4)
#define OFF_XH   83136      // half[64 rows * 160B] = 10240 (PERMUTED cols, fp16)
#define SMEM_DYN 93376

typedef unsigned long long ull;

__device__ __forceinline__ void up2(ull v, float& lo, float& hi) {
    asm("mov.b64 {%0, %1}, %2;" : "=f"(lo), "=f"(hi) : "l"(v));
}
__device__ __forceinline__ ull fma2(ull a, ull b, ull c) {
    ull d; asm("fma.rn.f32x2 %0, %1, %2, %3;" : "=l"(d) : "l"(a), "l"(b), "l"(c)); return d;
}
__device__ __forceinline__ uint32_t bf2(float vhi, float vlo) {
    uint32_t r; asm("cvt.rn.bf16x2.f32 %0, %1, %2;" : "=r"(r) : "f"(vhi), "f"(vlo)); return r;
}
__device__ __forceinline__ uint32_t hf2(float vhi, float vlo) {
    uint32_t r; asm("cvt.rn.f16x2.f32 %0, %1, %2;" : "=r"(r) : "f"(vhi), "f"(vlo)); return r;
}
__device__ __forceinline__ uint32_t hmul2(uint32_t a, uint32_t b) {
    uint32_t d; asm("mul.rn.f16x2 %0, %1, %2;" : "=r"(d) : "r"(a), "r"(b)); return d;
}
__device__ __forceinline__ void mma_h(float* c, uint32_t a0, uint32_t a1,
                                      uint32_t a2, uint32_t a3,
                                      uint32_t b0, uint32_t b1) {
    asm volatile(
        "mma.sync.aligned.m16n8k16.row.col.f32.f16.f16.f32 "
        "{%0,%1,%2,%3}, {%4,%5,%6,%7}, {%8,%9}, {%0,%1,%2,%3};"
        : "+f"(c[0]), "+f"(c[1]), "+f"(c[2]), "+f"(c[3])
        : "r"(a0), "r"(a1), "r"(a2), "r"(a3), "r"(b0), "r"(b1));
}
__device__ __forceinline__ void mma_b(float* c, uint32_t a0, uint32_t a1,
                                      uint32_t a2, uint32_t a3,
                                      uint32_t b0, uint32_t b1) {
    asm volatile(
        "mma.sync.aligned.m16n8k16.row.col.f32.bf16.bf16.f32 "
        "{%0,%1,%2,%3}, {%4,%5,%6,%7}, {%8,%9}, {%0,%1,%2,%3};"
        : "+f"(c[0]), "+f"(c[1]), "+f"(c[2]), "+f"(c[3])
        : "r"(a0), "r"(a1), "r"(a2), "r"(a3), "r"(b0), "r"(b1));
}
// column permutation within a 16-block: [0,1,8,9, 2,3,10,11, 4,5,12,13, 6,7,14,15]
__device__ __forceinline__ int pcol(int e) {
    int w = e & 15;
    return (e & 48) + ((w >> 1) & 3) * 4 + (w & 1) + ((w >> 3) << 1);
}

__global__ __launch_bounds__(NTHREADS, 2)
void afm_kernel(const float* __restrict__ x,    // (B, 64, 64)
                const float* __restrict__ W1,   // (64, 32)
                const float* __restrict__ b1,   // (32)
                const float* __restrict__ W2,   // (32, 1)
                const float* __restrict__ b2,   // (1)
                float* __restrict__ outP,       // (B, 64) or null
                float* __restrict__ attnP)      // (B, 2016) or null
{
    extern __shared__ char smx[];
    float*          xs   = (float*)(smx + OFF_XS);      // permuted fp32
    uint32_t*       W1h  = (uint32_t*)(smx + OFF_W1H);
    uint32_t*       W1l  = (uint32_t*)(smx + OFF_W1L);
    float*          lg   = (float*)(smx + OFF_LG);
    unsigned short* ijp  = (unsigned short*)(smx + OFF_IJP);
    uint32_t*       Xph  = (uint32_t*)(smx + OFF_XPH);
    uint32_t*       Xpl  = (uint32_t*)(smx + OFF_XPL);
    uint32_t*       Wph  = (uint32_t*)(smx + OFF_WPH);
    uint32_t*       Wpl  = (uint32_t*)(smx + OFF_WPL);
    uint32_t*       segt = (uint32_t*)(smx + OFF_SEG);
    uint16_t*       Wph16 = (uint16_t*)Wph;
    uint16_t*       Wpl16 = (uint16_t*)Wpl;
    float4*         bwq  = (float4*)(smx + OFF_MISC);   // {b1[2k],w2[2k],b1[2k+1],w2[2k+1]}
    float*          red  = (float*)(smx + OFF_MISC + 256);
    float*          b2sp = red + 8;

    const int t    = threadIdx.x;
    const int lane = t & 31;
    const int warp = t >> 5;
    const int b    = blockIdx.x;

    // ======================= prologue ======================================
    const float* xb = x + (size_t)b * (NF * EDIM);
    for (int idx = t; idx < NF * EDIM; idx += NTHREADS) {
        int f = idx >> 6, e = idx & 63;
        float v = xb[idx];
        int pe = pcol(e);
        xs[f * XSTR + pe] = v;
        *((__half*)(smx + OFF_XH + f * XHB) + pe) = __float2half(v);
    }
    // Xp: packed bf16x2 over field pairs (phase 3 operand)
    for (int idx = t; idx < 32 * 64; idx += NTHREADS) {
        int j2 = idx >> 6, e = idx & 63;
        float v0 = xb[(2 * j2) * EDIM + e];
        float v1 = xb[(2 * j2 + 1) * EDIM + e];
        uint32_t hi = bf2(v1, v0);
        float h0 = __uint_as_float(hi << 16);
        float h1 = __uint_as_float(hi & 0xFFFF0000u);
        Xph[j2 * XPS + e] = hi;
        Xpl[j2 * XPS + e] = bf2(v1 - h1, v0 - h0);
    }
    // W1 fp16 hi/lo: word[e2][a] = {W1[2e2+1][a] hi-half, W1[2e2][a] lo-half}
    for (int idx = t; idx < 32 * 32; idx += NTHREADS) {
        int e2 = idx >> 5, a = idx & 31;
        float v0 = W1[(2 * e2) * ADIM + a];
        float v1 = W1[(2 * e2 + 1) * ADIM + a];
        uint32_t hi = hf2(v1, v0);
        __half2 h2 = *(__half2*)&hi;
        float2 back = __half22float2(h2);
        W1h[e2 * 33 + a] = hi;
        W1l[e2 * 33 + a] = hf2(v1 - back.y, v0 - back.x);
    }
    // zero attn matrices
    for (int idx = t; idx < 64 * WPS; idx += NTHREADS) {
        Wph[idx] = 0u;
        Wpl[idx] = 0u;
    }
    if (t < 16) bwq[t] = make_float4(b1[2 * t], W2[2 * t], b1[2 * t + 1], W2[2 * t + 1]);
    if (t == 0) b2sp[0] = b2[0];
    // pair table + segment table
    if (t < NF - 1) {
        int i = t;
        int offi = i * 63 - (i * (i - 1)) / 2;
        for (int k = 0; k < NF - 1 - i; k++)
            ijp[offi + k] = (unsigned short)((i << 8) | (i + 1 + k));
        int q = i >> 4, r = i & 15;
        int S = 16 * (q * (q - 1) / 2) + q * (r + 1);
        int segbase = 4 * i - S;
        int first = (i + 1) >> 4;
        for (int s = first; s < 4; s++)
            segt[segbase + (s - first)] =
                (uint32_t)i | ((uint32_t)s << 6) | ((uint32_t)offi << 8);
    }
    if (t == 63) {
        for (int s = 0; s < 4; s++) segt[156 + s] = 63u | (3u << 6);
    }
    if (t >= 224) ijp[NPAIR + (t - 224)] = 0;
    __syncthreads();

    const float b2v = b2sp[0];
    const int tg = lane & 3;
    const int gr = lane >> 2;

    // hoisted B fragments (fp16 hi+lo, 64 regs) — zero W1 traffic in loop
    uint32_t bh0[4][4], bh1[4][4], bl0[4][4], bl1[4][4];
    #pragma unroll
    for (int kb = 0; kb < 4; kb++) {
        #pragma unroll
        for (int nb = 0; nb < 4; nb++) {
            int e2 = kb * 8 + tg;
            int a  = nb * 8 + gr;
            bh0[kb][nb] = W1h[e2 * 33 + a];
            bh1[kb][nb] = W1h[(e2 + 4) * 33 + a];
            bl0[kb][nb] = W1l[e2 * 33 + a];
            bl1[kb][nb] = W1l[(e2 + 4) * 33 + a];
        }
    }

    // ================= Phase 1: logits via fp16 mma (segments) =============
    for (int tt = 0; tt < NSEGT / 8; tt++) {
        const uint32_t sv = segt[tt * 8 + warp];
        const int i    = sv & 63;
        const int jb   = ((sv >> 6) & 3) << 4;
        const int offi = sv >> 8;

        // fp16 x rows: per kb block, this thread's 4 cols {2tg,2tg+1,2tg+8,2tg+9}
        // are contiguous 8 bytes at (kb*32 + tg*8) thanks to pcol permutation.
        const char* xiB  = smx + OFF_XH + i * XHB + tg * 8;
        const char* xj0B = smx + OFF_XH + (jb + gr) * XHB + tg * 8;
        const char* xj1B = smx + OFF_XH + (jb + gr + 8) * XHB + tg * 8;

        float c[4][4];
        #pragma unroll
        for (int nb = 0; nb < 4; nb++)
            c[nb][0] = c[nb][1] = c[nb][2] = c[nb][3] = 0.f;

        #pragma unroll
        for (int kb = 0; kb < 4; kb++) {
            const uint2 xiv = *(const uint2*)(xiB + kb * 32);
            const uint2 xj0 = *(const uint2*)(xj0B + kb * 32);
            const uint2 xj1 = *(const uint2*)(xj1B + kb * 32);
            const uint32_t a0 = hmul2(xj0.x, xiv.x);   // row gr,   k {2tg,2tg+1}
            const uint32_t a1 = hmul2(xj1.x, xiv.x);   // row gr+8, k {2tg,2tg+1}
            const uint32_t a2 = hmul2(xj0.y, xiv.y);   // row gr,   k {2tg+8,2tg+9}
            const uint32_t a3 = hmul2(xj1.y, xiv.y);   // row gr+8, k {2tg+8,2tg+9}
            #pragma unroll
            for (int nb = 0; nb < 4; nb++) {
                mma_h(c[nb], a0, a1, a2, a3, bh0[kb][nb], bh1[kb][nb]);
                mma_h(c[nb], a0, a1, a2, a3, bl0[kb][nb], bl1[kb][nb]);
            }
        }

        float s_lo = 0.f, s_hi = 0.f;
        #pragma unroll
        for (int nb = 0; nb < 4; nb++) {
            const float4 q = bwq[nb * 4 + tg];   // {b1[a],w2[a],b1[a+1],w2[a+1]}, a=nb*8+tg*2
            s_lo = fmaf(fmaxf(c[nb][0] + q.x, 0.f), q.y, s_lo);
            s_lo = fmaf(fmaxf(c[nb][1] + q.z, 0.f), q.w, s_lo);
            s_hi = fmaf(fmaxf(c[nb][2] + q.x, 0.f), q.y, s_hi);
            s_hi = fmaf(fmaxf(c[nb][3] + q.z, 0.f), q.w, s_hi);
        }
        s_lo += __shfl_xor_sync(0xFFFFFFFFu, s_lo, 1);
        s_lo += __shfl_xor_sync(0xFFFFFFFFu, s_lo, 2);
        s_hi += __shfl_xor_sync(0xFFFFFFFFu, s_hi, 1);
        s_hi += __shfl_xor_sync(0xFFFFFFFFu, s_hi, 2);
        if (tg == 0) {
            const int j0 = jb + gr;
            const int j1 = jb + gr + 8;
            if (j0 > i) lg[offi + j0 - i - 1] = s_lo + b2v;
            if (j1 > i) lg[offi + j1 - i - 1] = s_hi + b2v;
        }
    }
    __syncthreads();

    // ================= Phase 2: softmax ====================================
    float lmax = -3.402823466e+38f;
    for (int p = t; p < NPAIR; p += NTHREADS) lmax = fmaxf(lmax, lg[p]);
    #pragma unroll
    for (int o = 16; o > 0; o >>= 1) lmax = fmaxf(lmax, __shfl_xor_sync(0xFFFFFFFFu, lmax, o));
    if (lane == 0) red[warp] = lmax;
    __syncthreads();
    if (t == 0) {
        float m = red[0];
        #pragma unroll
        for (int w = 1; w < 8; w++) m = fmaxf(m, red[w]);
        red[0] = m;
    }
    __syncthreads();
    const float gmax = red[0];
    __syncthreads();

    float lsum = 0.f;
    for (int p = t; p < NPAIR; p += NTHREADS) {
        float ev = __expf(lg[p] - gmax);
        lg[p] = ev;
        lsum += ev;
    }
    #pragma unroll
    for (int o = 16; o > 0; o >>= 1) lsum += __shfl_xor_sync(0xFFFFFFFFu, lsum, o);
    if (lane == 0) red[warp] = lsum;
    __syncthreads();
    if (t == 0) {
        float s = 0.f;
        #pragma unroll
        for (int w = 0; w < 8; w++) s += red[w];
        red[0] = 1.0f / s;
    }
    __syncthreads();
    const float inv = red[0];

    // normalize + emit attn + scatter symmetric W (bf16 hi/lo)
    for (int p = t; p < NPAIR; p += NTHREADS) {
        float av = lg[p] * inv;
        if (attnP) attnP[(size_t)b * NPAIR + p] = av;
        const unsigned short ij = ijp[p];
        const int i = ij >> 8, j = ij & 255;
        uint32_t hpair = bf2(0.f, av);
        uint16_t hb = (uint16_t)(hpair & 0xFFFFu);
        float hv = __uint_as_float((uint32_t)hb << 16);
        uint32_t lpair = bf2(0.f, av - hv);
        uint16_t lb = (uint16_t)(lpair & 0xFFFFu);
        Wph16[i * (2 * WPS) + j] = hb;
        Wph16[j * (2 * WPS) + i] = hb;
        Wpl16[i * (2 * WPS) + j] = lb;
        Wpl16[j * (2 * WPS) + i] = lb;
    }
    __syncthreads();

    // ================= Phase 3: out = 0.5 * colsum(x .* (W@x)) =============
    if (outP) {
        float c[4][4];
        #pragma unroll
        for (int m = 0; m < 4; m++)
            c[m][0] = c[m][1] = c[m][2] = c[m][3] = 0.f;

        const int ecol = warp * 8 + gr;
        #pragma unroll
        for (int kb = 0; kb < 4; kb++) {
            const int j2a = kb * 8 + tg;
            uint32_t xh0 = Xph[j2a * XPS + ecol];
            uint32_t xh1 = Xph[(j2a + 4) * XPS + ecol];
            uint32_t xl0 = Xpl[j2a * XPS + ecol];
            uint32_t xl1 = Xpl[(j2a + 4) * XPS + ecol];
            #pragma unroll
            for (int m = 0; m < 4; m++) {
                const int r0 = (m * 16 + gr) * WPS;
                const int r1 = (m * 16 + gr + 8) * WPS;
                uint32_t ah0 = Wph[r0 + j2a];
                uint32_t ah1 = Wph[r1 + j2a];
                uint32_t ah2 = Wph[r0 + j2a + 4];
                uint32_t ah3 = Wph[r1 + j2a + 4];
                uint32_t al0 = Wpl[r0 + j2a];
                uint32_t al1 = Wpl[r1 + j2a];
                uint32_t al2 = Wpl[r0 + j2a + 4];
                uint32_t al3 = Wpl[r1 + j2a + 4];
                mma_b(c[m], ah0, ah1, ah2, ah3, xh0, xh1);
                mma_b(c[m], ah0, ah1, ah2, ah3, xl0, xl1);
                mma_b(c[m], al0, al1, al2, al3, xh0, xh1);
            }
        }

        const int e0 = warp * 8 + tg * 2;
        const int pe = pcol(e0);
        float pe0 = 0.f, pe1 = 0.f;
        #pragma unroll
        for (int m = 0; m < 4; m++) {
            const int i0 = m * 16 + gr;
            const int i1 = i0 + 8;
            float x00, x01, x10, x11;
            up2(*(const ull*)(xs + i0 * XSTR + pe), x00, x01);
            up2(*(const ull*)(xs + i1 * XSTR + pe), x10, x11);
            pe0 = fmaf(c[m][0], x00, pe0);
            pe1 = fmaf(c[m][1], x01, pe1);
            pe0 = fmaf(c[m][2], x10, pe0);
            pe1 = fmaf(c[m][3], x11, pe1);
        }
        #pragma unroll
        for (int o = 4; o < 32; o <<= 1) {
            pe0 += __shfl_xor_sync(0xFFFFFFFFu, pe0, o);
            pe1 += __shfl_xor_sync(0xFFFFFFFFu, pe1, o);
        }
        if (gr == 0) {
            outP[(size_t)b * EDIM + e0]     = 0.5f * pe0;
            outP[(size_t)b * EDIM + e0 + 1] = 0.5f * pe1;
        }
    }
}

extern "C" void kernel_launch(void* const* d_in, const int* in_sizes, int n_in,
                              void* d_out, int out_size) {
    const float* x  = (const float*)d_in[0];
    const float* W1 = (const float*)d_in[1];
    const float* b1 = (const float*)d_in[2];
    const float* W2 = (const float*)d_in[3];
    const float* b2 = (const float*)d_in[4];

    const int B = in_sizes[0] / (NF * EDIM);

    float* outP  = (float*)d_out;
    float* attnP = (float*)d_out + (size_t)B * EDIM;
    if (out_size == B * NPAIR) {           // attn only
        attnP = (float*)d_out;
        outP  = nullptr;
    } else if (out_size == B * EDIM) {     // outputs only
        attnP = nullptr;
    }

    cudaFuncSetAttribute(afm_kernel, cudaFuncAttributeMaxDynamicSharedMemorySize, SMEM_DYN);
    afm_kernel<<<B, NTHREADS, SMEM_DYN>>>(x, W1, b1, W2, b2, outP, attnP);
}

// round 17
// speedup vs baseline: 1.3680x; 1.1636x over previous
#include <cuda_runtime.h>
#include <cuda_bf16.h>
#include <cuda_fp16.h>
#include <cstdint>

// AFM layer via mma.sync (sm_80-class HMMA on sm_100 target). 2 CTAs/SM.
// B=1024, N=64 fields, E=64, A=32, P=2016 pairs.
//   Phase 1: logits = relu(inner@W1 + b1)@W2 + b2, fp16 mma SINGLE-term
//            (A and W1 both rnd-to-fp16; dropped corrections ~2^-12 rel).
//            A fragments via mul.f16x2 on fp16 x tile. Software-pipelined:
//            next tile's 12 LDS.64 issued before current tile's mma+epilogue.
//   Phase 2: softmax (__expf) + scatter symmetric attn matrix.
//   Phase 3: out = 0.5 * colsum( x .* (W@x) ), bf16 3-term mma (fp32 xs).

#define NF 64
#define EDIM 64
#define ADIM 32
#define NPAIR 2016
#define XSTR 80        // fp32 xs: 16B-chunk stride 4 mod 8 -> LDS.128 conflict-free
#define XHB 160        // fp16 xh row stride BYTES: conflict-free LDS.64
#define XPS 72
#define WPS 44
#define NTHREADS 256
#define NSEGT 160
#define NTILE 20       // NSEGT/8 tiles per warp

// dynamic smem layout (bytes)
#define OFF_XS   0          // float[64*80]  = 20480 (PERMUTED cols)
#define OFF_W1H  20480      // u32[32*33]    = 4224  (fp16x2, rnd16(W1))
#define OFF_LG   24704      // float[2048]   = 8192
#define OFF_IJP  32896      // u16[2048]     = 4096
#define OFF_XPH  36992      // u32[32*72]    = 9216
#define OFF_XPL  46208      // u32[32*72]    = 9216
#define OFF_WPH  55424      // u32[64*44]    = 11264
#define OFF_WPL  66688      // u32[64*44]    = 11264
#define OFF_SEG  77952      // u32[160]      = 640
#define OFF_MISC 78592      // bwq float4[16] (256) + red[8] (32) + b2 (4)
#define OFF_XH   78912      // half[64 rows * 160B] = 10240 (PERMUTED cols, fp16)
#define SMEM_DYN 89152

typedef unsigned long long ull;

__device__ __forceinline__ void up2(ull v, float& lo, float& hi) {
    asm("mov.b64 {%0, %1}, %2;" : "=f"(lo), "=f"(hi) : "l"(v));
}
__device__ __forceinline__ uint32_t bf2(float vhi, float vlo) {
    uint32_t r; asm("cvt.rn.bf16x2.f32 %0, %1, %2;" : "=r"(r) : "f"(vhi), "f"(vlo)); return r;
}
__device__ __forceinline__ uint32_t hf2(float vhi, float vlo) {
    uint32_t r; asm("cvt.rn.f16x2.f32 %0, %1, %2;" : "=r"(r) : "f"(vhi), "f"(vlo)); return r;
}
__device__ __forceinline__ uint32_t hmul2(uint32_t a, uint32_t b) {
    uint32_t d; asm("mul.rn.f16x2 %0, %1, %2;" : "=r"(d) : "r"(a), "r"(b)); return d;
}
__device__ __forceinline__ void mma_h(float* c, uint32_t a0, uint32_t a1,
                                      uint32_t a2, uint32_t a3,
                                      uint32_t b0, uint32_t b1) {
    asm volatile(
        "mma.sync.aligned.m16n8k16.row.col.f32.f16.f16.f32 "
        "{%0,%1,%2,%3}, {%4,%5,%6,%7}, {%8,%9}, {%0,%1,%2,%3};"
        : "+f"(c[0]), "+f"(c[1]), "+f"(c[2]), "+f"(c[3])
        : "r"(a0), "r"(a1), "r"(a2), "r"(a3), "r"(b0), "r"(b1));
}
__device__ __forceinline__ void mma_b(float* c, uint32_t a0, uint32_t a1,
                                      uint32_t a2, uint32_t a3,
                                      uint32_t b0, uint32_t b1) {
    asm volatile(
        "mma.sync.aligned.m16n8k16.row.col.f32.bf16.bf16.f32 "
        "{%0,%1,%2,%3}, {%4,%5,%6,%7}, {%8,%9}, {%0,%1,%2,%3};"
        : "+f"(c[0]), "+f"(c[1]), "+f"(c[2]), "+f"(c[3])
        : "r"(a0), "r"(a1), "r"(a2), "r"(a3), "r"(b0), "r"(b1));
}
// column permutation within a 16-block: [0,1,8,9, 2,3,10,11, 4,5,12,13, 6,7,14,15]
__device__ __forceinline__ int pcol(int e) {
    int w = e & 15;
    return (e & 48) + ((w >> 1) & 3) * 4 + (w & 1) + ((w >> 3) << 1);
}

__global__ __launch_bounds__(NTHREADS, 2)
void afm_kernel(const float* __restrict__ x,    // (B, 64, 64)
                const float* __restrict__ W1,   // (64, 32)
                const float* __restrict__ b1,   // (32)
                const float* __restrict__ W2,   // (32, 1)
                const float* __restrict__ b2,   // (1)
                float* __restrict__ outP,       // (B, 64) or null
                float* __restrict__ attnP)      // (B, 2016) or null
{
    extern __shared__ char smx[];
    float*          xs   = (float*)(smx + OFF_XS);      // permuted fp32
    uint32_t*       W1h  = (uint32_t*)(smx + OFF_W1H);
    float*          lg   = (float*)(smx + OFF_LG);
    unsigned short* ijp  = (unsigned short*)(smx + OFF_IJP);
    uint32_t*       Xph  = (uint32_t*)(smx + OFF_XPH);
    uint32_t*       Xpl  = (uint32_t*)(smx + OFF_XPL);
    uint32_t*       Wph  = (uint32_t*)(smx + OFF_WPH);
    uint32_t*       Wpl  = (uint32_t*)(smx + OFF_WPL);
    uint32_t*       segt = (uint32_t*)(smx + OFF_SEG);
    uint16_t*       Wph16 = (uint16_t*)Wph;
    uint16_t*       Wpl16 = (uint16_t*)Wpl;
    float4*         bwq  = (float4*)(smx + OFF_MISC);   // {b1[2k],w2[2k],b1[2k+1],w2[2k+1]}
    float*          red  = (float*)(smx + OFF_MISC + 256);
    float*          b2sp = red + 8;

    const int t    = threadIdx.x;
    const int lane = t & 31;
    const int warp = t >> 5;
    const int b    = blockIdx.x;

    // ======================= prologue ======================================
    const float* xb = x + (size_t)b * (NF * EDIM);
    for (int idx = t; idx < NF * EDIM; idx += NTHREADS) {
        int f = idx >> 6, e = idx & 63;
        float v = xb[idx];
        int pe = pcol(e);
        xs[f * XSTR + pe] = v;
        *((__half*)(smx + OFF_XH + f * XHB) + pe) = __float2half(v);
    }
    // Xp: packed bf16x2 over field pairs (phase 3 operand)
    for (int idx = t; idx < 32 * 64; idx += NTHREADS) {
        int j2 = idx >> 6, e = idx & 63;
        float v0 = xb[(2 * j2) * EDIM + e];
        float v1 = xb[(2 * j2 + 1) * EDIM + e];
        uint32_t hi = bf2(v1, v0);
        float h0 = __uint_as_float(hi << 16);
        float h1 = __uint_as_float(hi & 0xFFFF0000u);
        Xph[j2 * XPS + e] = hi;
        Xpl[j2 * XPS + e] = bf2(v1 - h1, v0 - h0);
    }
    // W1 fp16 (single precision level): word[e2][a] = {W1[2e2+1][a], W1[2e2][a]}
    for (int idx = t; idx < 32 * 32; idx += NTHREADS) {
        int e2 = idx >> 5, a = idx & 31;
        float v0 = W1[(2 * e2) * ADIM + a];
        float v1 = W1[(2 * e2 + 1) * ADIM + a];
        W1h[e2 * 33 + a] = hf2(v1, v0);
    }
    // zero attn matrices
    for (int idx = t; idx < 64 * WPS; idx += NTHREADS) {
        Wph[idx] = 0u;
        Wpl[idx] = 0u;
    }
    if (t < 16) bwq[t] = make_float4(b1[2 * t], W2[2 * t], b1[2 * t + 1], W2[2 * t + 1]);
    if (t == 0) b2sp[0] = b2[0];
    // pair table + segment table
    if (t < NF - 1) {
        int i = t;
        int offi = i * 63 - (i * (i - 1)) / 2;
        for (int k = 0; k < NF - 1 - i; k++)
            ijp[offi + k] = (unsigned short)((i << 8) | (i + 1 + k));
        int q = i >> 4, r = i & 15;
        int S = 16 * (q * (q - 1) / 2) + q * (r + 1);
        int segbase = 4 * i - S;
        int first = (i + 1) >> 4;
        for (int s = first; s < 4; s++)
            segt[segbase + (s - first)] =
                (uint32_t)i | ((uint32_t)s << 6) | ((uint32_t)offi << 8);
    }
    if (t == 63) {
        for (int s = 0; s < 4; s++) segt[156 + s] = 63u | (3u << 6);
    }
    if (t >= 224) ijp[NPAIR + (t - 224)] = 0;
    __syncthreads();

    const float b2v = b2sp[0];
    const int tg = lane & 3;
    const int gr = lane >> 2;

    // hoisted B fragments (fp16, 32 regs) — zero W1 traffic in loop
    uint32_t bh0[4][4], bh1[4][4];
    #pragma unroll
    for (int kb = 0; kb < 4; kb++) {
        #pragma unroll
        for (int nb = 0; nb < 4; nb++) {
            int e2 = kb * 8 + tg;
            int a  = nb * 8 + gr;
            bh0[kb][nb] = W1h[e2 * 33 + a];
            bh1[kb][nb] = W1h[(e2 + 4) * 33 + a];
        }
    }

    // ============ Phase 1: logits via fp16 mma, pipelined tiles ============
    uint32_t sv;
    uint2 fxi[4], fxj0[4], fxj1[4];
    // preload tile 0
    {
        sv = segt[warp];
        const int i  = sv & 63;
        const int jb = ((sv >> 6) & 3) << 4;
        const char* xiB  = smx + OFF_XH + i * XHB + tg * 8;
        const char* xj0B = smx + OFF_XH + (jb + gr) * XHB + tg * 8;
        const char* xj1B = smx + OFF_XH + (jb + gr + 8) * XHB + tg * 8;
        #pragma unroll
        for (int kb = 0; kb < 4; kb++) {
            fxi[kb]  = *(const uint2*)(xiB  + kb * 32);
            fxj0[kb] = *(const uint2*)(xj0B + kb * 32);
            fxj1[kb] = *(const uint2*)(xj1B + kb * 32);
        }
    }

    #pragma unroll
    for (int tt = 0; tt < NTILE; tt++) {
        // ---- issue next tile's loads early (overlap with mma+epilogue) ----
        uint32_t svn = 0;
        uint2 nxi[4], nxj0[4], nxj1[4];
        if (tt + 1 < NTILE) {
            svn = segt[(tt + 1) * 8 + warp];
            const int i  = svn & 63;
            const int jb = ((svn >> 6) & 3) << 4;
            const char* xiB  = smx + OFF_XH + i * XHB + tg * 8;
            const char* xj0B = smx + OFF_XH + (jb + gr) * XHB + tg * 8;
            const char* xj1B = smx + OFF_XH + (jb + gr + 8) * XHB + tg * 8;
            #pragma unroll
            for (int kb = 0; kb < 4; kb++) {
                nxi[kb]  = *(const uint2*)(xiB  + kb * 32);
                nxj0[kb] = *(const uint2*)(xj0B + kb * 32);
                nxj1[kb] = *(const uint2*)(xj1B + kb * 32);
            }
        }

        // ---- mma on current fragments ----
        float c[4][4];
        #pragma unroll
        for (int nb = 0; nb < 4; nb++)
            c[nb][0] = c[nb][1] = c[nb][2] = c[nb][3] = 0.f;

        #pragma unroll
        for (int kb = 0; kb < 4; kb++) {
            const uint32_t a0 = hmul2(fxj0[kb].x, fxi[kb].x);   // row gr,   k lo
            const uint32_t a1 = hmul2(fxj1[kb].x, fxi[kb].x);   // row gr+8, k lo
            const uint32_t a2 = hmul2(fxj0[kb].y, fxi[kb].y);   // row gr,   k hi
            const uint32_t a3 = hmul2(fxj1[kb].y, fxi[kb].y);   // row gr+8, k hi
            #pragma unroll
            for (int nb = 0; nb < 4; nb++)
                mma_h(c[nb], a0, a1, a2, a3, bh0[kb][nb], bh1[kb][nb]);
        }

        // ---- epilogue (uses current sv) ----
        const int i    = sv & 63;
        const int jb   = ((sv >> 6) & 3) << 4;
        const int offi = sv >> 8;
        float s_lo = 0.f, s_hi = 0.f;
        #pragma unroll
        for (int nb = 0; nb < 4; nb++) {
            const float4 q = bwq[nb * 4 + tg];   // {b1[a],w2[a],b1[a+1],w2[a+1]}, a=nb*8+tg*2
            s_lo = fmaf(fmaxf(c[nb][0] + q.x, 0.f), q.y, s_lo);
            s_lo = fmaf(fmaxf(c[nb][1] + q.z, 0.f), q.w, s_lo);
            s_hi = fmaf(fmaxf(c[nb][2] + q.x, 0.f), q.y, s_hi);
            s_hi = fmaf(fmaxf(c[nb][3] + q.z, 0.f), q.w, s_hi);
        }
        s_lo += __shfl_xor_sync(0xFFFFFFFFu, s_lo, 1);
        s_lo += __shfl_xor_sync(0xFFFFFFFFu, s_lo, 2);
        s_hi += __shfl_xor_sync(0xFFFFFFFFu, s_hi, 1);
        s_hi += __shfl_xor_sync(0xFFFFFFFFu, s_hi, 2);
        if (tg == 0) {
            const int j0 = jb + gr;
            const int j1 = jb + gr + 8;
            if (j0 > i) lg[offi + j0 - i - 1] = s_lo + b2v;
            if (j1 > i) lg[offi + j1 - i - 1] = s_hi + b2v;
        }

        // ---- rotate pipeline (renamed away under full unroll) ----
        sv = svn;
        #pragma unroll
        for (int kb = 0; kb < 4; kb++) {
            fxi[kb] = nxi[kb]; fxj0[kb] = nxj0[kb]; fxj1[kb] = nxj1[kb];
        }
    }
    __syncthreads();

    // ================= Phase 2: softmax ====================================
    float lmax = -3.402823466e+38f;
    for (int p = t; p < NPAIR; p += NTHREADS) lmax = fmaxf(lmax, lg[p]);
    #pragma unroll
    for (int o = 16; o > 0; o >>= 1) lmax = fmaxf(lmax, __shfl_xor_sync(0xFFFFFFFFu, lmax, o));
    if (lane == 0) red[warp] = lmax;
    __syncthreads();
    if (t == 0) {
        float m = red[0];
        #pragma unroll
        for (int w = 1; w < 8; w++) m = fmaxf(m, red[w]);
        red[0] = m;
    }
    __syncthreads();
    const float gmax = red[0];
    __syncthreads();

    float lsum = 0.f;
    for (int p = t; p < NPAIR; p += NTHREADS) {
        float ev = __expf(lg[p] - gmax);
        lg[p] = ev;
        lsum += ev;
    }
    #pragma unroll
    for (int o = 16; o > 0; o >>= 1) lsum += __shfl_xor_sync(0xFFFFFFFFu, lsum, o);
    if (lane == 0) red[warp] = lsum;
    __syncthreads();
    if (t == 0) {
        float s = 0.f;
        #pragma unroll
        for (int w = 0; w < 8; w++) s += red[w];
        red[0] = 1.0f / s;
    }
    __syncthreads();
    const float inv = red[0];

    // normalize + emit attn + scatter symmetric W (bf16 hi/lo)
    for (int p = t; p < NPAIR; p += NTHREADS) {
        float av = lg[p] * inv;
        if (attnP) attnP[(size_t)b * NPAIR + p] = av;
        const unsigned short ij = ijp[p];
        const int i = ij >> 8, j = ij & 255;
        uint32_t hpair = bf2(0.f, av);
        uint16_t hb = (uint16_t)(hpair & 0xFFFFu);
        float hv = __uint_as_float((uint32_t)hb << 16);
        uint32_t lpair = bf2(0.f, av - hv);
        uint16_t lb = (uint16_t)(lpair & 0xFFFFu);
        Wph16[i * (2 * WPS) + j] = hb;
        Wph16[j * (2 * WPS) + i] = hb;
        Wpl16[i * (2 * WPS) + j] = lb;
        Wpl16[j * (2 * WPS) + i] = lb;
    }
    __syncthreads();

    // ================= Phase 3: out = 0.5 * colsum(x .* (W@x)) =============
    if (outP) {
        float c[4][4];
        #pragma unroll
        for (int m = 0; m < 4; m++)
            c[m][0] = c[m][1] = c[m][2] = c[m][3] = 0.f;

        const int ecol = warp * 8 + gr;
        #pragma unroll
        for (int kb = 0; kb < 4; kb++) {
            const int j2a = kb * 8 + tg;
            uint32_t xh0 = Xph[j2a * XPS + ecol];
            uint32_t xh1 = Xph[(j2a + 4) * XPS + ecol];
            uint32_t xl0 = Xpl[j2a * XPS + ecol];
            uint32_t xl1 = Xpl[(j2a + 4) * XPS + ecol];
            #pragma unroll
            for (int m = 0; m < 4; m++) {
                const int r0 = (m * 16 + gr) * WPS;
                const int r1 = (m * 16 + gr + 8) * WPS;
                uint32_t ah0 = Wph[r0 + j2a];
                uint32_t ah1 = Wph[r1 + j2a];
                uint32_t ah2 = Wph[r0 + j2a + 4];
                uint32_t ah3 = Wph[r1 + j2a + 4];
                uint32_t al0 = Wpl[r0 + j2a];
                uint32_t al1 = Wpl[r1 + j2a];
                uint32_t al2 = Wpl[r0 + j2a + 4];
                uint32_t al3 = Wpl[r1 + j2a + 4];
                mma_b(c[m], ah0, ah1, ah2, ah3, xh0, xh1);
                mma_b(c[m], ah0, ah1, ah2, ah3, xl0, xl1);
                mma_b(c[m], al0, al1, al2, al3, xh0, xh1);
            }
        }

        const int e0 = warp * 8 + tg * 2;
        const int pe = pcol(e0);
        float pe0 = 0.f, pe1 = 0.f;
        #pragma unroll
        for (int m = 0; m < 4; m++) {
            const int i0 = m * 16 + gr;
            const int i1 = i0 + 8;
            float x00, x01, x10, x11;
            up2(*(const ull*)(xs + i0 * XSTR + pe), x00, x01);
            up2(*(const ull*)(xs + i1 * XSTR + pe), x10, x11);
            pe0 = fmaf(c[m][0], x00, pe0);
            pe1 = fmaf(c[m][1], x01, pe1);
            pe0 = fmaf(c[m][2], x10, pe0);
            pe1 = fmaf(c[m][3], x11, pe1);
        }
        #pragma unroll
        for (int o = 4; o < 32; o <<= 1) {
            pe0 += __shfl_xor_sync(0xFFFFFFFFu, pe0, o);
            pe1 += __shfl_xor_sync(0xFFFFFFFFu, pe1, o);
        }
        if (gr == 0) {
            outP[(size_t)b * EDIM + e0]     = 0.5f * pe0;
            outP[(size_t)b * EDIM + e0 + 1] = 0.5f * pe1;
        }
    }
}

extern "C" void kernel_launch(void* const* d_in, const int* in_sizes, int n_in,
                              void* d_out, int out_size) {
    const float* x  = (const float*)d_in[0];
    const float* W1 = (const float*)d_in[1];
    const float* b1 = (const float*)d_in[2];
    const float* W2 = (const float*)d_in[3];
    const float* b2 = (const float*)d_in[4];

    const int B = in_sizes[0] / (NF * EDIM);

    float* outP  = (float*)d_out;
    float* attnP = (float*)d_out + (size_t)B * EDIM;
    if (out_size == B * NPAIR) {           // attn only
        attnP = (float*)d_out;
        outP  = nullptr;
    } else if (out_size == B * EDIM) {     // outputs only
        attnP = nullptr;
    }

    cudaFuncSetAttribute(afm_kernel, cudaFuncAttributeMaxDynamicSharedMemorySize, SMEM_DYN);
    afm_kernel<<<B, NTHREADS, SMEM_DYN>>>(x, W1, b1, W2, b2, outP, attnP);
}